// round 2
// baseline (speedup 1.0000x reference)
#include <cuda_runtime.h>
#include <cuda_bf16.h>

// loss_i = logsumexp(x_i) - dot(w_raw(. - t_i), x_i) / S(t_i)
// w_raw(d) = MAIN (d==0), BASE + UB*2^-d (d>0), BASE (d<0)
// S(t) = MAIN + 8*BASE + UB*(1 - 2^{t-8})

static constexpr int   NUM_CLASSES = 9;
static constexpr float BASE_W = 0.1f / 9.0f;
static constexpr float MAIN_W = 1.0f - 0.1f - 0.2f;   // 0.7
static constexpr float UB     = 0.2f;
static constexpr int   BATCH  = 4000000;
static constexpr int   BLOCK  = 256;
static constexpr int   GRID   = 2048;

__device__ float g_partials[GRID];

// exact power of two 2^(-e) for 0 <= e <= 8, via exponent bits (no MUFU)
__device__ __forceinline__ float exp2_neg(int e) {
    return __uint_as_float((unsigned)(127 - e) << 23);
}

__global__ __launch_bounds__(BLOCK)
void ce_loss_kernel(const float* __restrict__ logits,
                    const int*   __restrict__ targets) {
    float acc = 0.0f;
    const long long stride = (long long)GRID * BLOCK;
    for (long long r = (long long)blockIdx.x * BLOCK + threadIdx.x;
         r < BATCH; r += stride) {
        const float* row = logits + r * NUM_CLASSES;
        float x[NUM_CLASSES];
        #pragma unroll
        for (int c = 0; c < NUM_CLASSES; c++) x[c] = __ldg(row + c);
        const int t = __ldg(targets + r);

        // logsumexp
        float m = x[0];
        #pragma unroll
        for (int c = 1; c < NUM_CLASSES; c++) m = fmaxf(m, x[c]);
        float se = 0.0f;
        #pragma unroll
        for (int c = 0; c < NUM_CLASSES; c++) se += __expf(x[c] - m);
        const float lse = m + __logf(se);

        // dot(w_raw, x)
        float dot = 0.0f;
        #pragma unroll
        for (int c = 0; c < NUM_CLASSES; c++) {
            const int d = c - t;
            float w;
            if (d == 0) {
                w = MAIN_W;
            } else if (d > 0) {
                w = BASE_W + UB * exp2_neg(d);
            } else {
                w = BASE_W;
            }
            dot = fmaf(w, x[c], dot);
        }

        // row-sum of raw labels (closed form)
        const float S = MAIN_W + 8.0f * BASE_W + UB * (1.0f - exp2_neg(8 - t));
        acc += lse - dot / S;
    }

    // deterministic block tree-reduce
    __shared__ float sm[BLOCK];
    sm[threadIdx.x] = acc;
    __syncthreads();
    #pragma unroll
    for (int s = BLOCK / 2; s > 0; s >>= 1) {
        if (threadIdx.x < s) sm[threadIdx.x] += sm[threadIdx.x + s];
        __syncthreads();
    }
    if (threadIdx.x == 0) g_partials[blockIdx.x] = sm[0];
}

__global__ __launch_bounds__(BLOCK)
void ce_reduce_kernel(float* __restrict__ out) {
    __shared__ float sm[BLOCK];
    float acc = 0.0f;
    for (int i = threadIdx.x; i < GRID; i += BLOCK) acc += g_partials[i];
    sm[threadIdx.x] = acc;
    __syncthreads();
    #pragma unroll
    for (int s = BLOCK / 2; s > 0; s >>= 1) {
        if (threadIdx.x < s) sm[threadIdx.x] += sm[threadIdx.x + s];
        __syncthreads();
    }
    if (threadIdx.x == 0) out[0] = sm[0] * (1.0f / (float)BATCH);
}

extern "C" void kernel_launch(void* const* d_in, const int* in_sizes, int n_in,
                              void* d_out, int out_size) {
    const float* logits  = (const float*)d_in[0];
    const int*   targets = (const int*)d_in[1];
    float*       out     = (float*)d_out;
    (void)in_sizes; (void)n_in; (void)out_size;

    ce_loss_kernel<<<GRID, BLOCK>>>(logits, targets);
    ce_reduce_kernel<<<1, BLOCK>>>(out);
}